// round 6
// baseline (speedup 1.0000x reference)
#include <cuda_runtime.h>
#include <cuda_bf16.h>
#include <math_constants.h>

#define B_DIM 64
#define S_DIM 512
#define H_DIM 4096
#define WARPS_PER_BLOCK 8
#define THREADS (WARPS_PER_BLOCK * 32)
#define ROWS_PER_TILE 8                       // one row per warp per tile
#define TILES_PER_BATCH (S_DIM / ROWS_PER_TILE)   // 64
#define N_TILES (B_DIM * TILES_PER_BATCH)         // 4096
#define GRID 592                                   // 148 SMs * 4 CTAs

// Scratch (no cudaMalloc allowed)
__device__ float        g_energies[B_DIM * S_DIM];
__device__ unsigned int g_counter[B_DIM];   // zero-init; reset by finishing block

__global__ __launch_bounds__(THREADS, 4)    // 64-reg budget -> 4 CTAs/SM
void fused_kernel(const float* __restrict__ questions,
                  const float* __restrict__ facts,
                  float* __restrict__ out) {
    __shared__ float4 sq[H_DIM / 4];          // 16 KB question row (1024 float4)
    __shared__ float  red[WARPS_PER_BLOCK];
    __shared__ float  bcast;
    __shared__ int    is_last;

    const int tid  = threadIdx.x;
    const int warp = tid >> 5;
    const int lane = tid & 31;

    // Contiguous tile range for this CTA (balanced within +/-1)
    const int t_begin = (int)(((long long)blockIdx.x     * N_TILES) / GRID);
    const int t_end   = (int)(((long long)(blockIdx.x+1) * N_TILES) / GRID);

    int b_cur = -1;
    int seg_count = 0;    // tiles of batch b_cur completed by this CTA

    for (int tile = t_begin; tile <= t_end; ++tile) {
        const int b = (tile < t_end) ? (tile / TILES_PER_BATCH) : -2;  // -2 = flush

        // ---- batch boundary: publish the finished segment, restage question ----
        if (b != b_cur) {
            if (b_cur >= 0) {
                // Make this CTA's energy stores (all warps) device-visible,
                // then bump the batch counter once for the whole segment.
                __threadfence();
                __syncthreads();
                if (tid == 0) {
                    unsigned prev = atomicAdd(&g_counter[b_cur], (unsigned)seg_count);
                    is_last = (prev + (unsigned)seg_count == TILES_PER_BATCH);
                    if (is_last) {
                        g_counter[b_cur] = 0;     // reset for next graph replay
                        __threadfence();
                    }
                }
                __syncthreads();

                if (is_last) {
                    // softmax over this batch's 512 energies (2 elems/thread)
                    const int base = b_cur * S_DIM;
                    float e0 = __ldcg(&g_energies[base + tid]);
                    float e1 = __ldcg(&g_energies[base + tid + THREADS]);

                    float m = fmaxf(e0, e1);
                    #pragma unroll
                    for (int off = 16; off > 0; off >>= 1)
                        m = fmaxf(m, __shfl_xor_sync(0xffffffffu, m, off));
                    if (lane == 0) red[warp] = m;
                    __syncthreads();
                    if (tid < 32) {
                        float v = (lane < WARPS_PER_BLOCK) ? red[lane] : -CUDART_INF_F;
                        #pragma unroll
                        for (int off = 16; off > 0; off >>= 1)
                            v = fmaxf(v, __shfl_xor_sync(0xffffffffu, v, off));
                        if (lane == 0) bcast = v;
                    }
                    __syncthreads();
                    const float row_max = bcast;

                    float x0 = __expf(e0 - row_max);
                    float x1 = __expf(e1 - row_max);
                    float ssum = x0 + x1;
                    #pragma unroll
                    for (int off = 16; off > 0; off >>= 1)
                        ssum += __shfl_xor_sync(0xffffffffu, ssum, off);
                    __syncthreads();
                    if (lane == 0) red[warp] = ssum;
                    __syncthreads();
                    if (tid < 32) {
                        float v = (lane < WARPS_PER_BLOCK) ? red[lane] : 0.f;
                        #pragma unroll
                        for (int off = 16; off > 0; off >>= 1)
                            v += __shfl_xor_sync(0xffffffffu, v, off);
                        if (lane == 0) bcast = v;
                    }
                    __syncthreads();
                    const float inv = 1.0f / bcast;

                    out[base + tid]           = x0 * inv;
                    out[base + tid + THREADS] = x1 * inv;
                    __syncthreads();
                }
            }
            if (b < 0) break;     // flush iteration: done

            // stage new question row
            if (b_cur != -1 && !(b_cur >= 0)) __syncthreads();
            const float4* qv = reinterpret_cast<const float4*>(
                questions + (size_t)b * H_DIM);
            for (int i = tid; i < H_DIM / 4; i += THREADS)
                sq[i] = qv[i];
            __syncthreads();
            b_cur = b;
            seg_count = 0;
        }

        // ---- one row per warp: 32 float4/lane as 4 rolled batches of 8 LDG.128 ----
        const int chunk = tile % TILES_PER_BATCH;
        const int s = chunk * ROWS_PER_TILE + warp;
        const float4* fv = reinterpret_cast<const float4*>(
            facts + ((size_t)b * S_DIM + s) * H_DIM);

        float a0 = 0.f, a1 = 0.f, a2 = 0.f, a3 = 0.f,
              a4 = 0.f, a5 = 0.f, a6 = 0.f, a7 = 0.f;

        #pragma unroll 1                       // rolled: MLP=8, regs in budget
        for (int j = 0; j < 4; ++j) {
            const float4* fp = fv + j * 256 + lane;    // 256 float4 per chunk
            const float4* qp = sq + j * 256 + lane;
            float4 f0 = __ldcs(fp + 0 * 32);
            float4 f1 = __ldcs(fp + 1 * 32);
            float4 f2 = __ldcs(fp + 2 * 32);
            float4 f3 = __ldcs(fp + 3 * 32);
            float4 f4 = __ldcs(fp + 4 * 32);
            float4 f5 = __ldcs(fp + 5 * 32);
            float4 f6 = __ldcs(fp + 6 * 32);
            float4 f7 = __ldcs(fp + 7 * 32);
            float4 q;
            q = qp[0 * 32];
            a0 = fmaf(f0.x, q.x, fmaf(f0.y, q.y, fmaf(f0.z, q.z, fmaf(f0.w, q.w, a0))));
            q = qp[1 * 32];
            a1 = fmaf(f1.x, q.x, fmaf(f1.y, q.y, fmaf(f1.z, q.z, fmaf(f1.w, q.w, a1))));
            q = qp[2 * 32];
            a2 = fmaf(f2.x, q.x, fmaf(f2.y, q.y, fmaf(f2.z, q.z, fmaf(f2.w, q.w, a2))));
            q = qp[3 * 32];
            a3 = fmaf(f3.x, q.x, fmaf(f3.y, q.y, fmaf(f3.z, q.z, fmaf(f3.w, q.w, a3))));
            q = qp[4 * 32];
            a4 = fmaf(f4.x, q.x, fmaf(f4.y, q.y, fmaf(f4.z, q.z, fmaf(f4.w, q.w, a4))));
            q = qp[5 * 32];
            a5 = fmaf(f5.x, q.x, fmaf(f5.y, q.y, fmaf(f5.z, q.z, fmaf(f5.w, q.w, a5))));
            q = qp[6 * 32];
            a6 = fmaf(f6.x, q.x, fmaf(f6.y, q.y, fmaf(f6.z, q.z, fmaf(f6.w, q.w, a6))));
            q = qp[7 * 32];
            a7 = fmaf(f7.x, q.x, fmaf(f7.y, q.y, fmaf(f7.z, q.z, fmaf(f7.w, q.w, a7))));
        }
        float acc = ((a0 + a1) + (a2 + a3)) + ((a4 + a5) + (a6 + a7));
        #pragma unroll
        for (int off = 16; off > 0; off >>= 1)
            acc += __shfl_xor_sync(0xffffffffu, acc, off);
        if (lane == 0)
            g_energies[b * S_DIM + s] = acc;

        ++seg_count;     // no block sync, no fence: pure streaming inner loop
    }
}

extern "C" void kernel_launch(void* const* d_in, const int* in_sizes, int n_in,
                              void* d_out, int out_size) {
    const float* questions = (const float*)d_in[0];
    const float* facts     = (const float*)d_in[1];
    if (n_in >= 2 && in_sizes[0] > in_sizes[1]) {   // facts is the big one
        questions = (const float*)d_in[1];
        facts     = (const float*)d_in[0];
    }
    float* out = (float*)d_out;

    fused_kernel<<<GRID, THREADS>>>(questions, facts, out);
}

// round 7
// speedup vs baseline: 1.0353x; 1.0353x over previous
#include <cuda_runtime.h>
#include <cuda_bf16.h>
#include <math_constants.h>

#define B_DIM 64
#define S_DIM 512
#define H_DIM 4096
#define WARPS_PER_BLOCK 8
#define THREADS (WARPS_PER_BLOCK * 32)
#define ROWS_PER_WARP 2
#define S_PER_BLOCK (WARPS_PER_BLOCK * ROWS_PER_WARP)   // 16
#define CHUNKS (S_DIM / S_PER_BLOCK)                     // 32 blocks per batch

// Scratch (no cudaMalloc allowed)
__device__ float        g_energies[B_DIM * S_DIM];
__device__ unsigned int g_counter[B_DIM];   // zero-init; reset by finishing block

__global__ __launch_bounds__(THREADS, 3)    // ~85-reg budget -> 3 CTAs/SM (best measured)
void fused_kernel(const float* __restrict__ questions,
                  const float* __restrict__ facts,
                  float* __restrict__ out) {
    __shared__ float red[WARPS_PER_BLOCK];
    __shared__ float bcast;
    __shared__ int   is_last;

    const int b      = blockIdx.x / CHUNKS;
    const int schunk = blockIdx.x % CHUNKS;
    const int tid    = threadIdx.x;
    const int warp   = tid >> 5;
    const int lane   = tid & 31;

    // Question row read directly through L1 (__ldg): all warps on batch b read
    // identical per-lane addresses -> L1-resident after first touch. No smem
    // staging => 32 MB of restaging DRAM traffic eliminated.
    const float4* qv = reinterpret_cast<const float4*>(
        questions + (size_t)b * H_DIM);

    // ---- energies: each warp computes ROWS_PER_WARP dot products over H=4096 ----
    #pragma unroll
    for (int t = 0; t < ROWS_PER_WARP; ++t) {
        const int s = schunk * S_PER_BLOCK + t * WARPS_PER_BLOCK + warp;
        const float4* fv = reinterpret_cast<const float4*>(
            facts + ((size_t)b * S_DIM + s) * H_DIM);

        float a0 = 0.f, a1 = 0.f, a2 = 0.f, a3 = 0.f;
        #pragma unroll 2
        for (int j = 0; j < (H_DIM / 4) / 32; j += 4) {
            float4 f0 = __ldcs(&fv[(j + 0) * 32 + lane]);
            float4 f1 = __ldcs(&fv[(j + 1) * 32 + lane]);
            float4 f2 = __ldcs(&fv[(j + 2) * 32 + lane]);
            float4 f3 = __ldcs(&fv[(j + 3) * 32 + lane]);
            float4 q0 = __ldg(&qv[(j + 0) * 32 + lane]);
            float4 q1 = __ldg(&qv[(j + 1) * 32 + lane]);
            float4 q2 = __ldg(&qv[(j + 2) * 32 + lane]);
            float4 q3 = __ldg(&qv[(j + 3) * 32 + lane]);
            a0 = fmaf(f0.x, q0.x, fmaf(f0.y, q0.y, fmaf(f0.z, q0.z, fmaf(f0.w, q0.w, a0))));
            a1 = fmaf(f1.x, q1.x, fmaf(f1.y, q1.y, fmaf(f1.z, q1.z, fmaf(f1.w, q1.w, a1))));
            a2 = fmaf(f2.x, q2.x, fmaf(f2.y, q2.y, fmaf(f2.z, q2.z, fmaf(f2.w, q2.w, a2))));
            a3 = fmaf(f3.x, q3.x, fmaf(f3.y, q3.y, fmaf(f3.z, q3.z, fmaf(f3.w, q3.w, a3))));
        }
        float acc = (a0 + a1) + (a2 + a3);
        #pragma unroll
        for (int off = 16; off > 0; off >>= 1)
            acc += __shfl_xor_sync(0xffffffffu, acc, off);
        if (lane == 0)
            g_energies[b * S_DIM + s] = acc;
    }

    // ---- publish: last block of this batch performs the softmax ----
    __threadfence();                 // all threads: order energy stores device-wide
    __syncthreads();
    if (tid == 0) {
        unsigned prev = atomicAdd(&g_counter[b], 1u);
        is_last = (prev == CHUNKS - 1);
        if (is_last) {
            g_counter[b] = 0;        // reset for next graph replay
            __threadfence();
        }
    }
    __syncthreads();
    if (!is_last) return;

    // ---- softmax over the batch's 512 energies (256 threads, 2 elems each) ----
    float e0 = __ldcg(&g_energies[b * S_DIM + tid]);
    float e1 = __ldcg(&g_energies[b * S_DIM + tid + THREADS]);

    float m = fmaxf(e0, e1);
    #pragma unroll
    for (int off = 16; off > 0; off >>= 1)
        m = fmaxf(m, __shfl_xor_sync(0xffffffffu, m, off));
    if (lane == 0) red[warp] = m;
    __syncthreads();
    if (tid < 32) {
        float v = (lane < WARPS_PER_BLOCK) ? red[lane] : -CUDART_INF_F;
        #pragma unroll
        for (int off = 16; off > 0; off >>= 1)
            v = fmaxf(v, __shfl_xor_sync(0xffffffffu, v, off));
        if (lane == 0) bcast = v;
    }
    __syncthreads();
    const float row_max = bcast;

    float x0 = __expf(e0 - row_max);
    float x1 = __expf(e1 - row_max);
    float ssum = x0 + x1;
    #pragma unroll
    for (int off = 16; off > 0; off >>= 1)
        ssum += __shfl_xor_sync(0xffffffffu, ssum, off);
    __syncthreads();
    if (lane == 0) red[warp] = ssum;
    __syncthreads();
    if (tid < 32) {
        float v = (lane < WARPS_PER_BLOCK) ? red[lane] : 0.f;
        #pragma unroll
        for (int off = 16; off > 0; off >>= 1)
            v += __shfl_xor_sync(0xffffffffu, v, off);
        if (lane == 0) bcast = v;
    }
    __syncthreads();
    const float inv = 1.0f / bcast;

    out[b * S_DIM + tid]           = x0 * inv;
    out[b * S_DIM + tid + THREADS] = x1 * inv;
}

extern "C" void kernel_launch(void* const* d_in, const int* in_sizes, int n_in,
                              void* d_out, int out_size) {
    const float* questions = (const float*)d_in[0];
    const float* facts     = (const float*)d_in[1];
    if (n_in >= 2 && in_sizes[0] > in_sizes[1]) {   // facts is the big one
        questions = (const float*)d_in[1];
        facts     = (const float*)d_in[0];
    }
    float* out = (float*)d_out;

    fused_kernel<<<B_DIM * CHUNKS, THREADS>>>(questions, facts, out);
}